// round 1
// baseline (speedup 1.0000x reference)
#include <cuda_runtime.h>
#include <math.h>

#define NB 2
#define NC 14
#define NCLS 13          // classes 1..13
#define NPAIR (NB*NCLS)  // 26
#define HPIX 128
#define WPIX 128

// seg bitmaps: [src(0=stud,1=teach)][b][cls-1][row 0..127][word 0..3]
__device__ unsigned int g_seg[2*NB*NCLS*128*4];
// per (pair, pass) partial sums: 26*4
__device__ float g_part[NPAIR*4];

// ---------------------------------------------------------------------------
// Kernel A: per-pixel argmax over C, compress per-class segmentation bitmaps.
// grid (128, 2), block 256. blockIdx.y: 0=student, 1=teacher.
// ---------------------------------------------------------------------------
__global__ void argmax_kernel(const float* __restrict__ stud,
                              const float* __restrict__ teach) {
    int p   = blockIdx.x * blockDim.x + threadIdx.x;   // 0..32767 = b*16384 + pix
    int src = blockIdx.y;
    const float* base = (src == 0) ? stud : teach;
    int b   = p >> 14;
    int pix = p & 16383;
    const float* ptr = base + (size_t)b * NC * 16384 + pix;

    float best = ptr[0];
    int   bi   = 0;
#pragma unroll
    for (int c = 1; c < NC; c++) {
        float v = ptr[(size_t)c * 16384];
        if (v > best) { best = v; bi = c; }   // first-max semantics (strict >)
    }

    unsigned lane = threadIdx.x & 31;
    int word = pix >> 5;   // 0..511 within the image
#pragma unroll
    for (int cls = 1; cls < NC; cls++) {
        unsigned m = __ballot_sync(0xffffffffu, bi == cls);
        if (lane == 0)
            g_seg[((src * NB + b) * NCLS + (cls - 1)) * 512 + word] = m;
    }
}

// ---------------------------------------------------------------------------
// Kernel B: one CTA per (pair, EDT-pass). 26*4 = 104 CTAs, 128 threads.
// pass 0: seeds = fg_pred       pass 1: seeds = ~fg_pred
// pass 2: seeds = et (fg_targ)  pass 3: seeds = ~et
// Accumulates sum_pixels diff2 * dt2(pass) into g_part[blockIdx.x].
// ---------------------------------------------------------------------------
__global__ void __launch_bounds__(128, 1)
pair_kernel(const float* __restrict__ stud) {
    extern __shared__ unsigned char smem[];
    float*         diff2 = (float*)smem;                           // [128][129]
    unsigned char* d1    = (unsigned char*)(diff2 + 128 * 129);    // [128][132]
    unsigned int*  segS  = (unsigned int*)(d1 + 128 * 132);        // 512 words
    unsigned int*  segT  = segS + 512;
    unsigned int*  esb   = segT + 512;
    unsigned int*  etb   = esb + 512;
    unsigned int*  fgP   = etb + 512;
    __shared__ float s_acc[128];

    int pair = blockIdx.x >> 2;
    int pass = blockIdx.x & 3;
    int b    = pair / NCLS;
    int cls  = 1 + (pair % NCLS);
    int t    = threadIdx.x;   // 0..127

    // Load seg bitmaps for this (b, cls)
    for (int k = t; k < 512; k += 128) {
        segS[k] = g_seg[((0 * NB + b) * NCLS + (cls - 1)) * 512 + k];
        segT[k] = g_seg[((1 * NB + b) * NCLS + (cls - 1)) * 512 + k];
    }
    __syncthreads();

    // Edge masks: m & ~erosion(m) with cross SE, border erodes (pad=false).
    // Thread t handles row t; bit j of word w = column 32w+j.
#pragma unroll
    for (int rep = 0; rep < 2; rep++) {
        const unsigned int* seg = rep ? segT : segS;
        unsigned int*       eo  = rep ? etb  : esb;
        unsigned cur[4], up[4], dn[4];
#pragma unroll
        for (int w = 0; w < 4; w++) {
            cur[w] = seg[t * 4 + w];
            up[w]  = (t > 0)   ? seg[(t - 1) * 4 + w] : 0u;
            dn[w]  = (t < 127) ? seg[(t + 1) * 4 + w] : 0u;
        }
#pragma unroll
        for (int w = 0; w < 4; w++) {
            unsigned lft = (cur[w] << 1) | (w > 0 ? (cur[w - 1] >> 31) : 0u);
            unsigned rgt = (cur[w] >> 1) | (w < 3 ? (cur[w + 1] << 31) : 0u);
            unsigned er  = cur[w] & up[w] & dn[w] & lft & rgt;
            eo[t * 4 + w] = cur[w] & ~er;
        }
    }
    __syncthreads();

    // diff2 tile + fg_pred bitmap. Warp wp handles rows [32wp, 32wp+32).
    {
        int wp = t >> 5, lane = t & 31;
        const float* lg = stud + ((size_t)(b * NC + cls) * 128) * 128;
        float fcls = (float)cls;
        for (int r = 0; r < 32; r++) {
            int i = wp * 32 + r;
#pragma unroll
            for (int k = 0; k < 4; k++) {
                int j = k * 32 + lane;
                float L = lg[i * 128 + j];                 // coalesced 128B
                unsigned es = (esb[i * 4 + k] >> lane) & 1u;
                unsigned et = (etb[i * 4 + k] >> lane) & 1u;
                float pred = es ? L : 0.f;
                float targ = et ? fcls : 0.f;              // pt==cls on et
                float d = pred - targ;
                diff2[i * 129 + j] = d * d;
                unsigned m = __ballot_sync(0xffffffffu, es && (L > 0.5f));
                if (lane == 0) fgP[i * 4 + k] = m;
            }
        }
    }
    __syncthreads();

    // EDT phase 1: per-column 1D nearest-seed distance (two-pass). 255 = INF.
    {
        const unsigned int* S = (pass < 2) ? fgP : etb;
        unsigned inv = (pass & 1) ? 0xffffffffu : 0u;
        int w = t >> 5, sh = t & 31;
        int d = 255;
        for (int i = 0; i < 128; i++) {
            unsigned bit = ((S[i * 4 + w] ^ inv) >> sh) & 1u;
            d = bit ? 0 : min(d + 1, 255);
            d1[i * 132 + t] = (unsigned char)d;
        }
        d = 255;
        for (int i = 127; i >= 0; i--) {
            unsigned bit = ((S[i * 4 + w] ^ inv) >> sh) & 1u;
            d = bit ? 0 : min(d + 1, 255);
            int cur = d1[i * 132 + t];
            if (d < cur) d1[i * 132 + t] = (unsigned char)d;
        }
    }
    __syncthreads();

    // EDT phase 2: exact integer Meijster per row + fused accumulation.
    // out[j] = min_q (j-q)^2 + g(q)^2, INF columns skipped (reference's 1e12
    // sentinels never win; all-INF rows happen only when the field is invalid
    // and must contribute 0, which falls out of q staying -1).
    {
        int gsq[128];
#pragma unroll 4
        for (int q = 0; q < 128; q++) {
            int v = d1[t * 132 + q];
            gsq[q] = (v == 255) ? (1 << 28) : v * v;
        }
        int sA[128], tA[128];
        int q = -1;
        for (int u = 0; u < 128; u++) {
            int fu = gsq[u];
            if (fu >= (1 << 28)) continue;
            if (q < 0) { q = 0; sA[0] = u; tA[0] = 0; continue; }
            while (q >= 0) {
                int sq_ = sA[q], tq_ = tA[q];
                int a = tq_ - sq_, c = tq_ - u;
                if (a * a + gsq[sq_] > c * c + fu) q--;
                else break;
            }
            if (q < 0) { q = 0; sA[0] = u; tA[0] = 0; }
            else {
                int sq_ = sA[q];
                int num = u * u - sq_ * sq_ + fu - gsq[sq_];   // >= 0 here
                int wsep = 1 + num / (2 * (u - sq_));
                if (wsep < 128) { q++; sA[q] = u; tA[q] = wsep; }
            }
        }
        float acc = 0.f;
        if (q >= 0) {
            for (int u = 127; u >= 0; u--) {
                int sq_ = sA[q];
                int du  = u - sq_;
                acc += diff2[t * 129 + u] * (float)(du * du + gsq[sq_]);
                if (u == tA[q]) q--;
            }
        }
        s_acc[t] = acc;
    }
    __syncthreads();

    // Deterministic tree reduction
    for (int ofs = 64; ofs > 0; ofs >>= 1) {
        if (t < ofs) s_acc[t] += s_acc[t + ofs];
        __syncthreads();
    }
    if (t == 0) g_part[blockIdx.x] = s_acc[0];
}

// ---------------------------------------------------------------------------
// Kernel C: deterministic final combine.
// ---------------------------------------------------------------------------
__global__ void finish_kernel(float* __restrict__ out) {
    if (threadIdx.x == 0 && blockIdx.x == 0) {
        float tot = 0.f;
        for (int p = 0; p < NPAIR; p++) {
            float hd = (g_part[4 * p + 0] + g_part[4 * p + 1] +
                        g_part[4 * p + 2] + g_part[4 * p + 3]) * (1.f / 16384.f);
            tot += logf(hd + 1.f);
        }
        out[0] = 0.5f * tot;   // (1 - LOSS_WEIGHT) * sum
    }
}

extern "C" void kernel_launch(void* const* d_in, const int* in_sizes, int n_in,
                              void* d_out, int out_size) {
    const float* stud  = (const float*)d_in[0];
    const float* teach = (const float*)d_in[1];
    float* out = (float*)d_out;

    const int SMEM = 128 * 129 * 4 + 128 * 132 + 5 * 512 * 4;   // 93184 B
    cudaFuncSetAttribute(pair_kernel,
                         cudaFuncAttributeMaxDynamicSharedMemorySize, SMEM);

    dim3 gA(32768 / 256, 2);
    argmax_kernel<<<gA, 256>>>(stud, teach);
    pair_kernel<<<NPAIR * 4, 128, SMEM>>>(stud);
    finish_kernel<<<1, 32>>>(out);
}

// round 2
// speedup vs baseline: 1.9555x; 1.9555x over previous
#include <cuda_runtime.h>
#include <math.h>

#define NB 2
#define NC 14
#define NCLS 13          // classes 1..13
#define NPAIR (NB*NCLS)  // 26
#define INF_D (1 << 28)

// per-pixel argmax labels: [src(0=stud,1=teach)][b][16384 pixels], uchar
__device__ uint4 g_pred4[2 * NB * 1024];   // 65536 bytes, uint4-aligned
// per (pair, pass) partial sums
__device__ float g_part[NPAIR * 4];

// ---------------------------------------------------------------------------
// Kernel A: per-pixel argmax over C=14, 4 pixels/thread via float4.
// 16384 threads: tid = src*8192 + b*4096 + p4.
// ---------------------------------------------------------------------------
__global__ void argmax_kernel(const float* __restrict__ stud,
                              const float* __restrict__ teach) {
    int tid = blockIdx.x * blockDim.x + threadIdx.x;   // 0..16383
    int src = tid >> 13;
    int rem = tid & 8191;
    int b   = rem >> 12;
    int p4  = rem & 4095;
    const float4* base =
        (const float4*)((src ? teach : stud) + (size_t)b * NC * 16384) + p4;

    float4 best = base[0];
    int bx = 0, by = 0, bz = 0, bw = 0;
#pragma unroll
    for (int c = 1; c < NC; c++) {
        float4 v = base[(size_t)c * 4096];
        if (v.x > best.x) { best.x = v.x; bx = c; }
        if (v.y > best.y) { best.y = v.y; by = c; }
        if (v.z > best.z) { best.z = v.z; bz = c; }
        if (v.w > best.w) { best.w = v.w; bw = c; }
    }
    unsigned packed = (unsigned)bx | ((unsigned)by << 8) |
                      ((unsigned)bz << 16) | ((unsigned)bw << 24);
    ((unsigned*)g_pred4)[tid] = packed;
}

// pack 4 byte-compare results into a nibble (bit0 = lowest byte)
__device__ __forceinline__ unsigned nib4(unsigned u, unsigned patt) {
    return ((__vcmpeq4(u, patt) & 0x01010101u) * 0x01020408u) >> 24;
}

// ---------------------------------------------------------------------------
// Kernel B: one CTA per (pair, EDT-pass). 26*4 = 104 CTAs, 128 threads.
// pass 0: seeds = fg_pred   pass 1: seeds = ~fg_pred
// pass 2: seeds = et        pass 3: seeds = ~et
// ---------------------------------------------------------------------------
__global__ void __launch_bounds__(128, 1)
pair_kernel(const float* __restrict__ stud) {
    extern __shared__ unsigned char smem[];
    float*        diff2 = (float*)smem;                       // 128*129 f32 = 66048
    unsigned int* gsq   = (unsigned int*)(diff2 + 128 * 129); // [col][row] stride 129: 66048
    unsigned int* stk   = gsq + 128 * 129;                    // [depth][thr] 128*128: 65536
    unsigned int* segS  = stk + 128 * 128;                    // 512 words each below
    unsigned int* segT  = segS + 512;
    unsigned int* esb   = segT + 512;
    unsigned int* etb   = esb + 512;
    unsigned int* fgP   = etb + 512;
    __shared__ float s_acc[128];

    int pair = blockIdx.x >> 2;
    int pass = blockIdx.x & 3;
    int b    = pair / NCLS;
    int cls  = 1 + (pair % NCLS);
    int t    = threadIdx.x;   // 0..127

    // --- Build seg bitmaps for this (b, cls) from g_pred bytes (row t) ---
    {
        const uint4* PS = g_pred4 + (size_t)(0 * NB + b) * 1024 + t * 8;
        const uint4* PT = g_pred4 + (size_t)(1 * NB + b) * 1024 + t * 8;
        unsigned patt = (unsigned)cls * 0x01010101u;
#pragma unroll
        for (int w = 0; w < 4; w++) {
            uint4 a = PS[w * 2], c4 = PS[w * 2 + 1];
            segS[t * 4 + w] =  nib4(a.x, patt)        | (nib4(a.y, patt) << 4)  |
                              (nib4(a.z, patt) << 8)  | (nib4(a.w, patt) << 12) |
                              (nib4(c4.x, patt) << 16)| (nib4(c4.y, patt) << 20)|
                              (nib4(c4.z, patt) << 24)| (nib4(c4.w, patt) << 28);
            uint4 d4 = PT[w * 2], e4 = PT[w * 2 + 1];
            segT[t * 4 + w] =  nib4(d4.x, patt)        | (nib4(d4.y, patt) << 4)  |
                              (nib4(d4.z, patt) << 8)  | (nib4(d4.w, patt) << 12) |
                              (nib4(e4.x, patt) << 16)| (nib4(e4.y, patt) << 20)|
                              (nib4(e4.z, patt) << 24)| (nib4(e4.w, patt) << 28);
        }
    }
    __syncthreads();

    // --- Edge masks: m & ~erosion(m), cross SE, borders erode ---
#pragma unroll
    for (int rep = 0; rep < 2; rep++) {
        const unsigned int* seg = rep ? segT : segS;
        unsigned int*       eo  = rep ? etb  : esb;
        unsigned cur[4], up[4], dn[4];
#pragma unroll
        for (int w = 0; w < 4; w++) {
            cur[w] = seg[t * 4 + w];
            up[w]  = (t > 0)   ? seg[(t - 1) * 4 + w] : 0u;
            dn[w]  = (t < 127) ? seg[(t + 1) * 4 + w] : 0u;
        }
#pragma unroll
        for (int w = 0; w < 4; w++) {
            unsigned lft = (cur[w] << 1) | (w > 0 ? (cur[w - 1] >> 31) : 0u);
            unsigned rgt = (cur[w] >> 1) | (w < 3 ? (cur[w + 1] << 31) : 0u);
            unsigned er  = cur[w] & up[w] & dn[w] & lft & rgt;
            eo[t * 4 + w] = cur[w] & ~er;
        }
    }
    __syncthreads();

    // --- diff2 tile + fg_pred bitmap ---
    {
        int wp = t >> 5, lane = t & 31;
        const float* lg = stud + ((size_t)(b * NC + cls) * 128) * 128;
        float fcls = (float)cls;
        for (int r = 0; r < 32; r++) {
            int i = wp * 32 + r;
#pragma unroll
            for (int k = 0; k < 4; k++) {
                int j = k * 32 + lane;
                float L = lg[i * 128 + j];
                unsigned es = (esb[i * 4 + k] >> lane) & 1u;
                unsigned et = (etb[i * 4 + k] >> lane) & 1u;
                float pred = es ? L : 0.f;
                float targ = et ? fcls : 0.f;
                float d = pred - targ;
                diff2[i * 129 + j] = d * d;
                unsigned m = __ballot_sync(0xffffffffu, es && (L > 0.5f));
                if (lane == 0) fgP[i * 4 + k] = m;
            }
        }
    }
    __syncthreads();

    // --- EDT phase 1: per-column 1D distance, squared, straight into gsq ---
    // gsq layout [col][row], stride 129 -> conflict-free both phases.
    {
        const unsigned int* S = (pass < 2) ? fgP : etb;
        unsigned inv = (pass & 1) ? 0xffffffffu : 0u;
        int w = t >> 5, sh = t & 31;
        int d = 255;
        for (int i = 0; i < 128; i++) {
            unsigned bit = ((S[i * 4 + w] ^ inv) >> sh) & 1u;
            d = bit ? 0 : min(d + 1, 255);
            gsq[t * 129 + i] = (d == 255) ? (unsigned)INF_D : (unsigned)(d * d);
        }
        d = 255;
        for (int i = 127; i >= 0; i--) {
            unsigned bit = ((S[i * 4 + w] ^ inv) >> sh) & 1u;
            d = bit ? 0 : min(d + 1, 255);
            unsigned v = (d == 255) ? (unsigned)INF_D : (unsigned)(d * d);
            if (v < gsq[t * 129 + i]) gsq[t * 129 + i] = v;
        }
    }
    __syncthreads();

    // --- EDT phase 2: exact integer Meijster per row, stacks in smem,
    //     top-of-stack cached in registers, fused accumulation. ---
    {
        int q = -1;
        int s_top = 0, t_top = 0, g_top = 0;
        int fu_next = (int)gsq[0 * 129 + t];
        for (int u = 0; u < 128; u++) {
            int fu = fu_next;
            if (u < 127) fu_next = (int)gsq[(u + 1) * 129 + t];
            if (fu >= INF_D) continue;
            if (q >= 0) {
                while (true) {
                    int a = t_top - s_top, c = t_top - u;
                    if (a * a + g_top > c * c + fu) {
                        q--;
                        if (q < 0) break;
                        unsigned pk = stk[q * 128 + t];
                        s_top = pk & 127;
                        t_top = (pk >> 7) & 255;
                        g_top = (int)(pk >> 15);
                    } else break;
                }
            }
            if (q < 0) {
                q = 0; s_top = u; t_top = 0; g_top = fu;
            } else {
                int num  = u * u - s_top * s_top + fu - g_top;   // >= 0 here
                int wsep = 1 + num / (2 * (u - s_top));
                if (wsep < 128) {
                    stk[q * 128 + t] =
                        (unsigned)s_top | ((unsigned)t_top << 7) |
                        ((unsigned)g_top << 15);
                    q++;
                    s_top = u; t_top = wsep; g_top = fu;
                }
            }
        }
        float acc = 0.f;
        if (q >= 0) {
            for (int u = 127; u >= 0; u--) {
                int du = u - s_top;
                acc += diff2[t * 129 + u] * (float)(du * du + g_top);
                if (u == t_top) {
                    q--;
                    if (q >= 0) {
                        unsigned pk = stk[q * 128 + t];
                        s_top = pk & 127;
                        t_top = (pk >> 7) & 255;
                        g_top = (int)(pk >> 15);
                    }
                }
            }
        }
        s_acc[t] = acc;
    }
    __syncthreads();

    for (int ofs = 64; ofs > 0; ofs >>= 1) {
        if (t < ofs) s_acc[t] += s_acc[t + ofs];
        __syncthreads();
    }
    if (t == 0) g_part[blockIdx.x] = s_acc[0];
}

// ---------------------------------------------------------------------------
// Kernel C: deterministic final combine.
// ---------------------------------------------------------------------------
__global__ void finish_kernel(float* __restrict__ out) {
    if (threadIdx.x == 0 && blockIdx.x == 0) {
        float tot = 0.f;
        for (int p = 0; p < NPAIR; p++) {
            float hd = (g_part[4 * p + 0] + g_part[4 * p + 1] +
                        g_part[4 * p + 2] + g_part[4 * p + 3]) * (1.f / 16384.f);
            tot += logf(hd + 1.f);
        }
        out[0] = 0.5f * tot;   // (1 - LOSS_WEIGHT) * sum
    }
}

extern "C" void kernel_launch(void* const* d_in, const int* in_sizes, int n_in,
                              void* d_out, int out_size) {
    const float* stud  = (const float*)d_in[0];
    const float* teach = (const float*)d_in[1];
    float* out = (float*)d_out;

    // diff2 66048 + gsq 66048 + stk 65536 + 5 bitmaps 10240 = 207872 B
    const int SMEM = 128 * 129 * 4 + 128 * 129 * 4 + 128 * 128 * 4 + 5 * 512 * 4;
    cudaFuncSetAttribute(pair_kernel,
                         cudaFuncAttributeMaxDynamicSharedMemorySize, SMEM);

    argmax_kernel<<<64, 256>>>(stud, teach);
    pair_kernel<<<NPAIR * 4, 128, SMEM>>>(stud);
    finish_kernel<<<1, 32>>>(out);
}

// round 3
// speedup vs baseline: 2.4745x; 1.2654x over previous
#include <cuda_runtime.h>
#include <math.h>

#define NB 2
#define NC 14
#define NCLS 13          // classes 1..13
#define NPAIR (NB*NCLS)  // 26
#define GS 130           // u16 row stride for gsq/tmpB (65 words, odd -> conflict-free)

// per-pixel argmax labels: [src(0=stud,1=teach)][b][16384 pixels], uchar
__device__ uint4 g_pred4[2 * NB * 1024];   // 65536 bytes
// per (pair, pass) partial sums
__device__ float g_part[NPAIR * 4];

// ---------------------------------------------------------------------------
// Kernel A: per-pixel argmax over C=14, 2 pixels/thread via float2. 32768 thr.
// ---------------------------------------------------------------------------
__global__ void argmax_kernel(const float* __restrict__ stud,
                              const float* __restrict__ teach) {
    int tid = blockIdx.x * blockDim.x + threadIdx.x;   // 0..32767
    int src = tid >> 14;
    int rem = tid & 16383;
    int b   = rem >> 13;
    int p2  = rem & 8191;
    const float2* base =
        (const float2*)((src ? teach : stud) + (size_t)b * NC * 16384) + p2;

    float2 best = base[0];
    int bx = 0, by = 0;
#pragma unroll
    for (int c = 1; c < NC; c++) {
        float2 v = base[(size_t)c * 8192];
        if (v.x > best.x) { best.x = v.x; bx = c; }
        if (v.y > best.y) { best.y = v.y; by = c; }
    }
    ((unsigned short*)g_pred4)[tid] =
        (unsigned short)((unsigned)bx | ((unsigned)by << 8));
}

// pack 4 byte-compare results into a nibble (bit0 = lowest byte)
__device__ __forceinline__ unsigned nib4(unsigned u, unsigned patt) {
    return ((__vcmpeq4(u, patt) & 0x01010101u) * 0x01020408u) >> 24;
}

// ---------------------------------------------------------------------------
// Kernel B: one CTA per (pair, EDT-pass). 104 CTAs, 256 threads.
// pass 0: seeds = fg_pred   pass 1: seeds = ~fg_pred
// pass 2: seeds = et        pass 3: seeds = ~et
// ---------------------------------------------------------------------------
__global__ void __launch_bounds__(256, 1)
pair_kernel(const float* __restrict__ stud) {
    extern __shared__ unsigned char smem[];
    float*          diff2 = (float*)smem;                         // 128*129 f32
    unsigned short* gsq   = (unsigned short*)(diff2 + 128 * 129); // [row][GS]
    unsigned short* tmpB  = gsq + 128 * GS;                       // [row][GS]
    unsigned int*   segS  = (unsigned int*)(tmpB + 128 * GS);     // 512 words ea
    unsigned int*   segT  = segS + 512;
    unsigned int*   esb   = segT + 512;
    unsigned int*   etb   = esb + 512;
    unsigned int*   fgP   = etb + 512;
    __shared__ float s_acc[256];
    __shared__ int   s_carF[2 * 128];
    __shared__ int   s_carB[2 * 128];
    __shared__ int   s_any;

    int pair = blockIdx.x >> 2;
    int pass = blockIdx.x & 3;
    int b    = pair / NCLS;
    int cls  = 1 + (pair % NCLS);
    int t    = threadIdx.x;   // 0..255

    if (t == 0) s_any = 0;

    // --- Build seg bitmaps from g_pred bytes (threads 0-127, row = t) ---
    if (t < 128) {
        const uint4* PS = g_pred4 + (size_t)(0 * NB + b) * 1024 + t * 8;
        const uint4* PT = g_pred4 + (size_t)(1 * NB + b) * 1024 + t * 8;
        unsigned patt = (unsigned)cls * 0x01010101u;
#pragma unroll
        for (int w = 0; w < 4; w++) {
            uint4 a = PS[w * 2], c4 = PS[w * 2 + 1];
            segS[t * 4 + w] =  nib4(a.x, patt)        | (nib4(a.y, patt) << 4)  |
                              (nib4(a.z, patt) << 8)  | (nib4(a.w, patt) << 12) |
                              (nib4(c4.x, patt) << 16)| (nib4(c4.y, patt) << 20)|
                              (nib4(c4.z, patt) << 24)| (nib4(c4.w, patt) << 28);
            uint4 d4 = PT[w * 2], e4 = PT[w * 2 + 1];
            segT[t * 4 + w] =  nib4(d4.x, patt)        | (nib4(d4.y, patt) << 4)  |
                              (nib4(d4.z, patt) << 8)  | (nib4(d4.w, patt) << 12) |
                              (nib4(e4.x, patt) << 16)| (nib4(e4.y, patt) << 20)|
                              (nib4(e4.z, patt) << 24)| (nib4(e4.w, patt) << 28);
        }
    }
    __syncthreads();

    // --- Edge masks: m & ~erosion(m), cross SE, borders erode ---
    if (t < 128) {
#pragma unroll
        for (int rep = 0; rep < 2; rep++) {
            const unsigned int* seg = rep ? segT : segS;
            unsigned int*       eo  = rep ? etb  : esb;
            unsigned cur[4], up[4], dn[4];
#pragma unroll
            for (int w = 0; w < 4; w++) {
                cur[w] = seg[t * 4 + w];
                up[w]  = (t > 0)   ? seg[(t - 1) * 4 + w] : 0u;
                dn[w]  = (t < 127) ? seg[(t + 1) * 4 + w] : 0u;
            }
#pragma unroll
            for (int w = 0; w < 4; w++) {
                unsigned lft = (cur[w] << 1) | (w > 0 ? (cur[w - 1] >> 31) : 0u);
                unsigned rgt = (cur[w] >> 1) | (w < 3 ? (cur[w + 1] << 31) : 0u);
                unsigned er  = cur[w] & up[w] & dn[w] & lft & rgt;
                eo[t * 4 + w] = cur[w] & ~er;
            }
        }
    }
    __syncthreads();

    // --- diff2 tile + fg_pred bitmap (8 warps x 16 rows) ---
    {
        int wp = t >> 5, lane = t & 31;
        const float* lg = stud + ((size_t)(b * NC + cls) * 128) * 128;
        float fcls = (float)cls;
        for (int r = 0; r < 16; r++) {
            int i = wp * 16 + r;
#pragma unroll
            for (int k = 0; k < 4; k++) {
                int j = k * 32 + lane;
                float L = lg[i * 128 + j];
                unsigned es = (esb[i * 4 + k] >> lane) & 1u;
                unsigned et = (etb[i * 4 + k] >> lane) & 1u;
                float pred = es ? L : 0.f;
                float targ = et ? fcls : 0.f;
                float d = pred - targ;
                diff2[i * 129 + j] = d * d;
                unsigned m = __ballot_sync(0xffffffffu, es && (L > 0.5f));
                if (lane == 0) fgP[i * 4 + k] = m;
            }
        }
    }
    __syncthreads();

    const unsigned int* S = (pass < 2) ? fgP : etb;
    unsigned inv = (pass & 1) ? 0xffffffffu : 0u;

    // --- any-seed guard ---
    {
        unsigned m = 0;
        for (int k = t; k < 512; k += 256) m |= (S[k] ^ inv);
        if (__ballot_sync(0xffffffffu, m != 0) && (t & 31) == 0)
            atomicOr(&s_any, 1);
    }

    // --- EDT phase 1: column 1D distance, 2 row-segments of 64 ---
    {
        int c = t & 127, s = t >> 7;
        int i0 = s * 64;
        int w = c >> 5, sh = c & 31;
        int d = 255;
        for (int i = i0; i < i0 + 64; i++) {
            unsigned bit = ((S[i * 4 + w] ^ inv) >> sh) & 1u;
            d = bit ? 0 : min(d + 1, 255);
            gsq[i * GS + c] = (unsigned short)d;      // raw local fwd dist
        }
        s_carF[s * 128 + c] = d;
        int db = 255;
        for (int i = i0 + 63; i >= i0; i--) {
            unsigned bit = ((S[i * 4 + w] ^ inv) >> sh) & 1u;
            db = bit ? 0 : min(db + 1, 255);
            tmpB[i * GS + c] = (unsigned short)db;    // raw local bwd dist
        }
        s_carB[s * 128 + c] = db;
        __syncthreads();
        // apply cross-segment carries, combine, square
        int cF = s ? s_carF[0 * 128 + c] : 255;       // fwd carry into seg1
        int cB = s ? 255 : s_carB[1 * 128 + c];       // bwd carry into seg0
        for (int k = 0; k < 64; k++) {
            int i = i0 + k;
            int dm = min((int)gsq[i * GS + c], (int)tmpB[i * GS + c]);
            dm = min(dm, cF + k + 1);                 // seg0: cF=255 -> >=256
            dm = min(dm, cB + 64 - k);
            int sq = (dm >= 255) ? 65025 : dm * dm;   // 65025 = INF marker
            gsq[i * GS + c] = (unsigned short)sq;
        }
    }
    __syncthreads();

    // --- EDT phase 2: exact adaptive ring search + fused accumulation ---
    {
        float acc = 0.f;
        if (s_any) {
            int row = t & 127;
            int cb  = (t >> 7) * 64;
            const unsigned short* g = gsq + row * GS;
            const float* d2r = diff2 + row * 129;
            for (int jj = 0; jj < 64; jj++) {
                int j = cb + jj;
                int best = g[j];
#pragma unroll 1
                for (int r = 1; r < 128; r++) {
                    int r2 = r * r;
                    if (r2 >= best) break;
                    int lo = (r <= j)      ? (int)g[j - r] : 70000;
                    int hi = (j + r < 128) ? (int)g[j + r] : 70000;
                    int cand = min(lo, hi) + r2;
                    best = min(best, cand);
                }
                float dt2 = (best < 40000) ? (float)best : 0.f;
                acc += d2r[j] * dt2;
            }
        }
        s_acc[t] = acc;
    }
    __syncthreads();

    for (int ofs = 128; ofs > 0; ofs >>= 1) {
        if (t < ofs) s_acc[t] += s_acc[t + ofs];
        __syncthreads();
    }
    if (t == 0) g_part[blockIdx.x] = s_acc[0];
}

// ---------------------------------------------------------------------------
// Kernel C: deterministic final combine.
// ---------------------------------------------------------------------------
__global__ void finish_kernel(float* __restrict__ out) {
    if (threadIdx.x == 0 && blockIdx.x == 0) {
        float tot = 0.f;
        for (int p = 0; p < NPAIR; p++) {
            float hd = (g_part[4 * p + 0] + g_part[4 * p + 1] +
                        g_part[4 * p + 2] + g_part[4 * p + 3]) * (1.f / 16384.f);
            tot += logf(hd + 1.f);
        }
        out[0] = 0.5f * tot;   // (1 - LOSS_WEIGHT) * sum
    }
}

extern "C" void kernel_launch(void* const* d_in, const int* in_sizes, int n_in,
                              void* d_out, int out_size) {
    const float* stud  = (const float*)d_in[0];
    const float* teach = (const float*)d_in[1];
    float* out = (float*)d_out;

    // diff2 66048 + gsq 33280 + tmpB 33280 + 5 bitmaps 10240 = 142848 B
    const int SMEM = 128 * 129 * 4 + 2 * 128 * GS * 2 + 5 * 512 * 4;
    cudaFuncSetAttribute(pair_kernel,
                         cudaFuncAttributeMaxDynamicSharedMemorySize, SMEM);

    argmax_kernel<<<128, 256>>>(stud, teach);
    pair_kernel<<<NPAIR * 4, 256, SMEM>>>(stud);
    finish_kernel<<<1, 32>>>(out);
}

// round 4
// speedup vs baseline: 5.1175x; 2.0681x over previous
#include <cuda_runtime.h>
#include <math.h>

#define NB 2
#define NC 14
#define NCLS 13          // classes 1..13
#define NPAIR (NB*NCLS)  // 26
#define GS 130           // u16 stride for gT (65 words, odd -> conflict-free)

// per-pixel argmax labels: [src(0=stud,1=teach)][b][16384 pixels]
__device__ __align__(16) unsigned char g_pred[2 * NB * 16384];
__device__ float g_part[NPAIR * 4];
__device__ int   g_counter = 0;

// ---------------------------------------------------------------------------
// Kernel A: per-pixel argmax over C=14. 65536 threads, 1 px each (max MLP).
// ---------------------------------------------------------------------------
__global__ void argmax_kernel(const float* __restrict__ stud,
                              const float* __restrict__ teach) {
    int tid = blockIdx.x * blockDim.x + threadIdx.x;   // 0..65535
    int src = tid >> 15;
    int rem = tid & 32767;          // b*16384 + pix
    const float* base = (src ? teach : stud) +
                        (size_t)(rem >> 14) * NC * 16384 + (rem & 16383);
    float best = base[0];
    int bi = 0;
#pragma unroll
    for (int c = 1; c < NC; c++) {
        float v = base[(size_t)c * 16384];
        if (v > best) { best = v; bi = c; }
    }
    g_pred[tid] = (unsigned char)bi;
}

// pack 4 byte-compare results into a nibble (bit0 = lowest byte)
__device__ __forceinline__ unsigned nib4(unsigned u, unsigned patt) {
    return ((__vcmpeq4(u, patt) & 0x01010101u) * 0x01020408u) >> 24;
}

// ---------------------------------------------------------------------------
// Kernel B: one CTA per (pair, EDT-pass). 104 CTAs, 512 threads.
// pass 0: seeds = fg_pred   pass 1: seeds = ~fg_pred
// pass 2: seeds = et        pass 3: seeds = ~et
// Last CTA also performs the final log-combine (fused finish).
// ---------------------------------------------------------------------------
__global__ void __launch_bounds__(512, 1)
pair_kernel(const float* __restrict__ stud, float* __restrict__ out) {
    extern __shared__ unsigned char smem[];
    float*          diff2 = (float*)smem;                         // 128*129 f32
    unsigned short* gT    = (unsigned short*)(diff2 + 128 * 129); // [col j][row i]
    unsigned int*   segS  = (unsigned int*)(gT + 128 * GS);       // 512 words ea
    unsigned int*   segT  = segS + 512;
    unsigned int*   esb   = segT + 512;
    unsigned int*   etb   = esb + 512;
    unsigned int*   fgP   = etb + 512;
    __shared__ float s_acc[512];

    int pair = blockIdx.x >> 2;
    int pass = blockIdx.x & 3;
    int b    = pair / NCLS;
    int cls  = 1 + (pair % NCLS);
    int t    = threadIdx.x;   // 0..511

    // --- Build seg bitmaps from g_pred bytes (threads 0-127, row = t) ---
    if (t < 128) {
        const uint4* PS = (const uint4*)(g_pred + (size_t)(0 * NB + b) * 16384) + t * 8;
        const uint4* PT = (const uint4*)(g_pred + (size_t)(1 * NB + b) * 16384) + t * 8;
        unsigned patt = (unsigned)cls * 0x01010101u;
#pragma unroll
        for (int w = 0; w < 4; w++) {
            uint4 a = PS[w * 2], c4 = PS[w * 2 + 1];
            segS[t * 4 + w] =  nib4(a.x, patt)        | (nib4(a.y, patt) << 4)  |
                              (nib4(a.z, patt) << 8)  | (nib4(a.w, patt) << 12) |
                              (nib4(c4.x, patt) << 16)| (nib4(c4.y, patt) << 20)|
                              (nib4(c4.z, patt) << 24)| (nib4(c4.w, patt) << 28);
            uint4 d4 = PT[w * 2], e4 = PT[w * 2 + 1];
            segT[t * 4 + w] =  nib4(d4.x, patt)        | (nib4(d4.y, patt) << 4)  |
                              (nib4(d4.z, patt) << 8)  | (nib4(d4.w, patt) << 12) |
                              (nib4(e4.x, patt) << 16)| (nib4(e4.y, patt) << 20)|
                              (nib4(e4.z, patt) << 24)| (nib4(e4.w, patt) << 28);
        }
    }
    __syncthreads();

    // --- Edge masks: m & ~erosion(m), cross SE, borders erode ---
    if (t < 128) {
#pragma unroll
        for (int rep = 0; rep < 2; rep++) {
            const unsigned int* seg = rep ? segT : segS;
            unsigned int*       eo  = rep ? etb  : esb;
            unsigned cur[4], up[4], dn[4];
#pragma unroll
            for (int w = 0; w < 4; w++) {
                cur[w] = seg[t * 4 + w];
                up[w]  = (t > 0)   ? seg[(t - 1) * 4 + w] : 0u;
                dn[w]  = (t < 127) ? seg[(t + 1) * 4 + w] : 0u;
            }
#pragma unroll
            for (int w = 0; w < 4; w++) {
                unsigned lft = (cur[w] << 1) | (w > 0 ? (cur[w - 1] >> 31) : 0u);
                unsigned rgt = (cur[w] >> 1) | (w < 3 ? (cur[w + 1] << 31) : 0u);
                unsigned er  = cur[w] & up[w] & dn[w] & lft & rgt;
                eo[t * 4 + w] = cur[w] & ~er;
            }
        }
    }
    __syncthreads();

    // --- diff2 tile + fg_pred bitmap (16 warps x 8 rows) ---
    {
        int wp = t >> 5, lane = t & 31;
        const float* lg = stud + ((size_t)(b * NC + cls) * 128) * 128;
        float fcls = (float)cls;
        for (int r = 0; r < 8; r++) {
            int i = wp * 8 + r;
#pragma unroll
            for (int k = 0; k < 4; k++) {
                int j = k * 32 + lane;
                float L = lg[i * 128 + j];
                unsigned es = (esb[i * 4 + k] >> lane) & 1u;
                unsigned et = (etb[i * 4 + k] >> lane) & 1u;
                float pred = es ? L : 0.f;
                float targ = et ? fcls : 0.f;
                float d = pred - targ;
                diff2[i * 129 + j] = d * d;
                unsigned m = __ballot_sync(0xffffffffu, es && (L > 0.5f));
                if (lane == 0) fgP[i * 4 + k] = m;
            }
        }
    }
    __syncthreads();

    const unsigned int* S = (pass < 2) ? fgP : etb;
    unsigned inv = (pass & 1) ? 0xffffffffu : 0u;

    // any-seed guard (barrier doubles as the sync after fgP writes)
    int any = __syncthreads_or((int)(S[t] ^ inv));

    // --- Phase 1: horizontal 1D nearest-seed distance via bit ops. ---
    // Thread t: row i = t&127, word/quarter qd = t>>7 (columns 32qd..32qd+31).
    // Writes squared distance to gT[j][i] (transposed).
    {
        int i  = t & 127;
        int qd = t >> 7;
        unsigned W[4];
#pragma unroll
        for (int w = 0; w < 4; w++) W[w] = S[i * 4 + w] ^ inv;
        unsigned Wq = W[qd];
        // highest set bit strictly below word qd
        int lpos = -100000;
        for (int w = qd - 1; w >= 0; w--)
            if (W[w]) { lpos = 32 * w + (31 - __clz(W[w])); break; }
        // lowest set bit strictly above word qd
        int rpos = 100000;
        for (int w = qd + 1; w < 4; w++)
            if (W[w]) { rpos = 32 * w + (__ffs(W[w]) - 1); break; }

        int jbase = qd * 32;
#pragma unroll 4
        for (int jj = 0; jj < 32; jj++) {
            int j = jbase + jj;
            unsigned mL = Wq & (0xFFFFFFFFu >> (31 - jj));   // bits 0..jj
            unsigned mR = Wq >> jj;                          // bits jj..31
            int dl = mL ? (jj - (31 - __clz(mL))) : (j - lpos);
            int dr = mR ? (__ffs(mR) - 1)         : (rpos - j);
            int d  = min(dl, dr);
            gT[j * GS + i] = (unsigned short)((d > 127) ? 65025 : d * d);
        }
    }
    __syncthreads();

    // --- Phase 2: exact adaptive ring search along columns + accumulate ---
    {
        float acc = 0.f;
        if (any) {
            int j  = t & 127;
            int ib = (t >> 7) * 32;
            const unsigned short* g = gT + j * GS;
            for (int ii = 0; ii < 32; ii++) {
                int i = ib + ii;
                int best = g[i];
#pragma unroll 1
                for (int r = 1; r < 128; r++) {
                    int r2 = r * r;
                    if (r2 >= best) break;
                    int lo = (r <= i)      ? (int)g[i - r] : 70000;
                    int hi = (i + r < 128) ? (int)g[i + r] : 70000;
                    best = min(best, min(lo, hi) + r2);
                }
                float dt2 = (best < 40000) ? (float)best : 0.f;
                acc += diff2[i * 129 + j] * dt2;
            }
        }
        s_acc[t] = acc;
    }
    __syncthreads();

    for (int ofs = 256; ofs > 0; ofs >>= 1) {
        if (t < ofs) s_acc[t] += s_acc[t + ofs];
        __syncthreads();
    }

    // --- fused finish: last CTA combines all partials ---
    if (t == 0) {
        g_part[blockIdx.x] = s_acc[0];
        __threadfence();
        if (atomicAdd(&g_counter, 1) == NPAIR * 4 - 1) {
            __threadfence();
            volatile float* vp = g_part;
            float tot = 0.f;
            for (int p = 0; p < NPAIR; p++) {
                float hd = (vp[4 * p + 0] + vp[4 * p + 1] +
                            vp[4 * p + 2] + vp[4 * p + 3]) * (1.f / 16384.f);
                tot += logf(hd + 1.f);
            }
            out[0] = 0.5f * tot;   // (1 - LOSS_WEIGHT) * sum
            g_counter = 0;         // self-reset -> deterministic replays
        }
    }
}

extern "C" void kernel_launch(void* const* d_in, const int* in_sizes, int n_in,
                              void* d_out, int out_size) {
    const float* stud  = (const float*)d_in[0];
    const float* teach = (const float*)d_in[1];
    float* out = (float*)d_out;

    // diff2 66048 + gT 33280 + 5 bitmaps 10240 = 109568 B
    const int SMEM = 128 * 129 * 4 + 128 * GS * 2 + 5 * 512 * 4;
    cudaFuncSetAttribute(pair_kernel,
                         cudaFuncAttributeMaxDynamicSharedMemorySize, SMEM);

    argmax_kernel<<<256, 256>>>(stud, teach);
    pair_kernel<<<NPAIR * 4, 512, SMEM>>>(stud, out);
}

// round 5
// speedup vs baseline: 7.0317x; 1.3741x over previous
#include <cuda_runtime.h>
#include <math.h>

#define NB 2
#define NC 14
#define NCLS 13          // classes 1..13
#define NPAIR (NB*NCLS)  // 26
#define GS 130           // u16 stride for gT (65 words, odd -> conflict-free)

// per-pixel argmax labels: [src(0=stud,1=teach)][b][16384 pixels]
__device__ __align__(16) unsigned char g_pred[2 * NB * 16384];
// per-pair bitmaps: [pair][0=es,1=et,2=fgP][512 words]
__device__ unsigned int g_masks[NPAIR][3][512];
__device__ float g_part[NPAIR * 4];
__device__ int   g_counter = 0;

// ---------------------------------------------------------------------------
// Kernel A: per-pixel argmax over C=14. 65536 threads, 1 px each (max MLP).
// ---------------------------------------------------------------------------
__global__ void argmax_kernel(const float* __restrict__ stud,
                              const float* __restrict__ teach) {
    int tid = blockIdx.x * blockDim.x + threadIdx.x;   // 0..65535
    int src = tid >> 15;
    int rem = tid & 32767;          // b*16384 + pix
    const float* base = (src ? teach : stud) +
                        (size_t)(rem >> 14) * NC * 16384 + (rem & 16383);
    float best = base[0];
    int bi = 0;
#pragma unroll
    for (int c = 1; c < NC; c++) {
        float v = base[(size_t)c * 16384];
        if (v > best) { best = v; bi = c; }
    }
    g_pred[tid] = (unsigned char)bi;
}

// pack 4 byte-compare results into a nibble (bit0 = lowest byte)
__device__ __forceinline__ unsigned nib4(unsigned u, unsigned patt) {
    return ((__vcmpeq4(u, patt) & 0x01010101u) * 0x01020408u) >> 24;
}

// ---------------------------------------------------------------------------
// Kernel P: one CTA per pair. Builds es / et / fgP bitmaps once (shared by
// the 4 pass-CTAs of pair_kernel).
// ---------------------------------------------------------------------------
__global__ void __launch_bounds__(512, 1)
prep_kernel(const float* __restrict__ stud) {
    __shared__ unsigned segS[512], segT[512], esb[512], etb[512];
    int pair = blockIdx.x;
    int b    = pair / NCLS;
    int cls  = 1 + (pair % NCLS);
    int t    = threadIdx.x;

    if (t < 128) {
        const uint4* PS = (const uint4*)(g_pred + (size_t)(0 * NB + b) * 16384) + t * 8;
        const uint4* PT = (const uint4*)(g_pred + (size_t)(1 * NB + b) * 16384) + t * 8;
        unsigned patt = (unsigned)cls * 0x01010101u;
#pragma unroll
        for (int w = 0; w < 4; w++) {
            uint4 a = PS[w * 2], c4 = PS[w * 2 + 1];
            segS[t * 4 + w] =  nib4(a.x, patt)        | (nib4(a.y, patt) << 4)  |
                              (nib4(a.z, patt) << 8)  | (nib4(a.w, patt) << 12) |
                              (nib4(c4.x, patt) << 16)| (nib4(c4.y, patt) << 20)|
                              (nib4(c4.z, patt) << 24)| (nib4(c4.w, patt) << 28);
            uint4 d4 = PT[w * 2], e4 = PT[w * 2 + 1];
            segT[t * 4 + w] =  nib4(d4.x, patt)        | (nib4(d4.y, patt) << 4)  |
                              (nib4(d4.z, patt) << 8)  | (nib4(d4.w, patt) << 12) |
                              (nib4(e4.x, patt) << 16)| (nib4(e4.y, patt) << 20)|
                              (nib4(e4.z, patt) << 24)| (nib4(e4.w, patt) << 28);
        }
    }
    __syncthreads();

    // Edge masks: m & ~erosion(m), cross SE, borders erode
    if (t < 128) {
#pragma unroll
        for (int rep = 0; rep < 2; rep++) {
            const unsigned* seg = rep ? segT : segS;
            unsigned*       eo  = rep ? etb  : esb;
            unsigned cur[4], up[4], dn[4];
#pragma unroll
            for (int w = 0; w < 4; w++) {
                cur[w] = seg[t * 4 + w];
                up[w]  = (t > 0)   ? seg[(t - 1) * 4 + w] : 0u;
                dn[w]  = (t < 127) ? seg[(t + 1) * 4 + w] : 0u;
            }
#pragma unroll
            for (int w = 0; w < 4; w++) {
                unsigned lft = (cur[w] << 1) | (w > 0 ? (cur[w - 1] >> 31) : 0u);
                unsigned rgt = (cur[w] >> 1) | (w < 3 ? (cur[w + 1] << 31) : 0u);
                unsigned er  = cur[w] & up[w] & dn[w] & lft & rgt;
                eo[t * 4 + w] = cur[w] & ~er;
            }
        }
    }
    __syncthreads();

    // fgP = es & (L > 0.5): 16 warps x 8 rows, coalesced logit loads + ballot
    {
        int wp = t >> 5, lane = t & 31;
        const float* lg = stud + (size_t)(b * NC + cls) * 16384;
        for (int r = 0; r < 8; r++) {
            int i = wp * 8 + r;
#pragma unroll
            for (int k = 0; k < 4; k++) {
                float L = lg[i * 128 + k * 32 + lane];
                unsigned es = (esb[i * 4 + k] >> lane) & 1u;
                unsigned m  = __ballot_sync(0xffffffffu, es && (L > 0.5f));
                if (lane == 0) g_masks[pair][2][i * 4 + k] = m;
            }
        }
    }
    g_masks[pair][0][t] = esb[t];
    g_masks[pair][1][t] = etb[t];
}

// ---------------------------------------------------------------------------
// Kernel B: one CTA per (pair, EDT-pass). 104 CTAs, 512 threads.
// pass 0: seeds = fgP   pass 1: seeds = ~fgP
// pass 2: seeds = et    pass 3: seeds = ~et
// Sparse accumulation: only pixels in es|et contribute (diff2 == 0 elsewhere).
// Last CTA performs the final log-combine.
// ---------------------------------------------------------------------------
__global__ void __launch_bounds__(512, 1)
pair_kernel(const float* __restrict__ stud, float* __restrict__ out) {
    __shared__ unsigned short gT[128 * GS];   // [col j][row i] squared 1D dist
    __shared__ unsigned Sm[512];              // seed bitmap (xor'ed)
    __shared__ float s_warp[16];

    int pair = blockIdx.x >> 2;
    int pass = blockIdx.x & 3;
    int b    = pair / NCLS;
    int cls  = 1 + (pair % NCLS);
    int t    = threadIdx.x;   // 0..511

    unsigned ew = g_masks[pair][0][t];
    unsigned tw = g_masks[pair][1][t];
    unsigned inv = (pass & 1) ? 0xffffffffu : 0u;
    unsigned sv  = ((pass < 2) ? g_masks[pair][2][t] : tw) ^ inv;
    Sm[t] = sv;
    int any = __syncthreads_or(sv != 0u);

    // --- Phase 1: horizontal 1D nearest-seed distance via bit ops ---
    // Thread t: row i = t&127, quarter qd = t>>7 (columns 32qd..32qd+31).
    {
        int i  = t & 127;
        int qd = t >> 7;
        unsigned W[4];
#pragma unroll
        for (int w = 0; w < 4; w++) W[w] = Sm[i * 4 + w];
        unsigned Wq = W[qd];
        int lpos = -100000;
        for (int w = qd - 1; w >= 0; w--)
            if (W[w]) { lpos = 32 * w + (31 - __clz(W[w])); break; }
        int rpos = 100000;
        for (int w = qd + 1; w < 4; w++)
            if (W[w]) { rpos = 32 * w + (__ffs(W[w]) - 1); break; }

        int jbase = qd * 32;
#pragma unroll 4
        for (int jj = 0; jj < 32; jj++) {
            int j = jbase + jj;
            unsigned mL = Wq & (0xFFFFFFFFu >> (31 - jj));
            unsigned mR = Wq >> jj;
            int dl = mL ? (jj - (31 - __clz(mL))) : (j - lpos);
            int dr = mR ? (__ffs(mR) - 1)         : (rpos - j);
            int d  = min(dl, dr);
            gT[j * GS + i] = (unsigned short)((d > 127) ? 65025 : d * d);
        }
    }
    __syncthreads();

    // --- Phase 2: sparse — ring search only at pixels where diff2 != 0 ---
    float acc = 0.f;
    if (any) {
        unsigned m = ew | tw;                 // word t: row i = t>>2, cols 32*(t&3)..
        int i     = t >> 2;
        int jbase = (t & 3) * 32;
        const float* lg = stud + (size_t)(b * NC + cls) * 16384 + i * 128;
        float fcls = (float)cls;
        while (m) {
            int bit = __ffs(m) - 1;
            m &= m - 1;
            int j = jbase + bit;
            float pred = ((ew >> bit) & 1u) ? lg[j] : 0.f;
            float targ = ((tw >> bit) & 1u) ? fcls : 0.f;
            float d = pred - targ;
            const unsigned short* g = gT + j * GS;
            int best = g[i];
#pragma unroll 1
            for (int r = 1; r < 128; r++) {
                int r2 = r * r;
                if (r2 >= best) break;
                int lo = (r <= i)      ? (int)g[i - r] : 70000;
                int hi = (i + r < 128) ? (int)g[i + r] : 70000;
                best = min(best, min(lo, hi) + r2);
            }
            float dt2 = (best < 40000) ? (float)best : 0.f;
            acc += d * d * dt2;
        }
    }

    // --- warp-shuffle reduction (2 barriers total) ---
#pragma unroll
    for (int o = 16; o; o >>= 1) acc += __shfl_down_sync(0xffffffffu, acc, o);
    if ((t & 31) == 0) s_warp[t >> 5] = acc;
    __syncthreads();

    if (t == 0) {
        float tot = 0.f;
#pragma unroll
        for (int k = 0; k < 16; k++) tot += s_warp[k];
        g_part[blockIdx.x] = tot;
        __threadfence();
        if (atomicAdd(&g_counter, 1) == NPAIR * 4 - 1) {
            __threadfence();
            volatile float* vp = g_part;
            float sum = 0.f;
            for (int p = 0; p < NPAIR; p++) {
                float hd = (vp[4 * p + 0] + vp[4 * p + 1] +
                            vp[4 * p + 2] + vp[4 * p + 3]) * (1.f / 16384.f);
                sum += logf(hd + 1.f);
            }
            out[0] = 0.5f * sum;   // (1 - LOSS_WEIGHT) * sum
            g_counter = 0;         // self-reset -> deterministic replays
        }
    }
}

extern "C" void kernel_launch(void* const* d_in, const int* in_sizes, int n_in,
                              void* d_out, int out_size) {
    const float* stud  = (const float*)d_in[0];
    const float* teach = (const float*)d_in[1];
    float* out = (float*)d_out;

    argmax_kernel<<<256, 256>>>(stud, teach);
    prep_kernel<<<NPAIR, 512>>>(stud);
    pair_kernel<<<NPAIR * 4, 512>>>(stud, out);
}

// round 6
// speedup vs baseline: 7.1067x; 1.0107x over previous
#include <cuda_runtime.h>
#include <math.h>

#define NB 2
#define NC 14
#define NCLS 13          // classes 1..13
#define NPAIR (NB*NCLS)  // 26
#define GS 130           // u16 stride for gT (65 words, odd -> conflict-free)
#define NCTA 148
#define NTHR 512
#define NLBL (2*NB*16384)   // 131072 labels (student+teacher)

// per-pixel argmax labels: [src(0=stud,1=teach)][b][16384 pixels]
__device__ __align__(16) unsigned char g_pred[NLBL];
__device__ float g_part[NPAIR * 4];
__device__ int   g_counter = 0;   // finish counter (self-resetting)
__device__ int   g_cnt     = 0;   // barrier ticket counter (self-resetting)
__device__ int   g_release = 0;   // barrier sense flag (flips each launch)

// pack 4 byte-compare results into a nibble (bit0 = lowest byte)
__device__ __forceinline__ unsigned nib4(unsigned u, unsigned patt) {
    return ((__vcmpeq4(u, patt) & 0x01010101u) * 0x01020408u) >> 24;
}

__global__ void __launch_bounds__(NTHR, 1)
fused_kernel(const float* __restrict__ stud,
             const float* __restrict__ teach,
             float* __restrict__ out) {
    // sbuf serves two disjoint-in-time roles:
    //   early: segS/segT/esb/etb bitmaps (16 KB)
    //   late:  gT[col j][row i] squared 1D distances (33280 B)
    __shared__ __align__(16) unsigned char sbuf[128 * GS * 2];
    __shared__ unsigned Sm[512];
    __shared__ float s_warp[16];

    unsigned short* gT   = (unsigned short*)sbuf;
    unsigned*       segS = (unsigned*)sbuf;
    unsigned*       segT = segS + 512;
    unsigned*       esb  = segT + 512;
    unsigned*       etb  = esb + 512;

    int t   = threadIdx.x;
    int bid = blockIdx.x;

    // read barrier sense BEFORE any arrival can flip it (flip requires our
    // own arrival, which is program-ordered after this read + fence below)
    int my_sense = 0;
    if (t == 0) my_sense = *(volatile int*)&g_release;

    // ---- Stage A: per-pixel argmax over C=14, all sources ----
    for (int idx = bid * NTHR + t; idx < NLBL; idx += NCTA * NTHR) {
        int src = idx >> 15;
        int rem = idx & 32767;               // b*16384 + pix
        const float* base = (src ? teach : stud) +
                            (size_t)(rem >> 14) * NC * 16384 + (rem & 16383);
        float best = base[0];
        int bi = 0;
#pragma unroll
        for (int c = 1; c < NC; c++) {
            float v = base[(size_t)c * 16384];
            if (v > best) { best = v; bi = c; }
        }
        g_pred[idx] = (unsigned char)bi;
    }

    // ---- grid-wide sense-reversing barrier (148 co-resident CTAs) ----
    __threadfence();        // make this thread's g_pred writes device-visible
    __syncthreads();
    if (t == 0) {
        __threadfence();    // order sense-read before arrival
        int ticket = atomicAdd(&g_cnt, 1);
        if (ticket == NCTA - 1) {
            g_cnt = 0;                       // reset for next replay
            __threadfence();
            atomicExch(&g_release, my_sense ^ 1);
        } else {
            while (*(volatile int*)&g_release == my_sense) __nanosleep(32);
        }
        __threadfence();
    }
    __syncthreads();

    if (bid >= NPAIR * 4) return;            // 44 helper CTAs done

    // ---- Stage B: one CTA per (pair, pass) ----
    int pair = bid >> 2;
    int pass = bid & 3;
    int b    = pair / NCLS;
    int cls  = 1 + (pair % NCLS);

    // build seg bitmaps from labels (threads 0-127, row = t)
    if (t < 128) {
        const uint4* PS = (const uint4*)(g_pred + (size_t)b        * 16384) + t * 8;
        const uint4* PT = (const uint4*)(g_pred + (size_t)(NB + b) * 16384) + t * 8;
        unsigned patt = (unsigned)cls * 0x01010101u;
#pragma unroll
        for (int w = 0; w < 4; w++) {
            uint4 a = PS[w * 2], c4 = PS[w * 2 + 1];
            segS[t * 4 + w] =  nib4(a.x, patt)        | (nib4(a.y, patt) << 4)  |
                              (nib4(a.z, patt) << 8)  | (nib4(a.w, patt) << 12) |
                              (nib4(c4.x, patt) << 16)| (nib4(c4.y, patt) << 20)|
                              (nib4(c4.z, patt) << 24)| (nib4(c4.w, patt) << 28);
            uint4 d4 = PT[w * 2], e4 = PT[w * 2 + 1];
            segT[t * 4 + w] =  nib4(d4.x, patt)        | (nib4(d4.y, patt) << 4)  |
                              (nib4(d4.z, patt) << 8)  | (nib4(d4.w, patt) << 12) |
                              (nib4(e4.x, patt) << 16)| (nib4(e4.y, patt) << 20)|
                              (nib4(e4.z, patt) << 24)| (nib4(e4.w, patt) << 28);
        }
    }
    __syncthreads();

    // edge masks: m & ~erosion(m), cross SE, borders erode
    if (t < 128) {
#pragma unroll
        for (int rep = 0; rep < 2; rep++) {
            const unsigned* seg = rep ? segT : segS;
            unsigned*       eo  = rep ? etb  : esb;
            unsigned cur[4], up[4], dn[4];
#pragma unroll
            for (int w = 0; w < 4; w++) {
                cur[w] = seg[t * 4 + w];
                up[w]  = (t > 0)   ? seg[(t - 1) * 4 + w] : 0u;
                dn[w]  = (t < 127) ? seg[(t + 1) * 4 + w] : 0u;
            }
#pragma unroll
            for (int w = 0; w < 4; w++) {
                unsigned lft = (cur[w] << 1) | (w > 0 ? (cur[w - 1] >> 31) : 0u);
                unsigned rgt = (cur[w] >> 1) | (w < 3 ? (cur[w + 1] << 31) : 0u);
                unsigned er  = cur[w] & up[w] & dn[w] & lft & rgt;
                eo[t * 4 + w] = cur[w] & ~er;
            }
        }
    }
    __syncthreads();

    // word t: row i = t>>2, cols (t&3)*32 .. +31
    unsigned ew = esb[t];
    unsigned tw = etb[t];
    int i     = t >> 2;
    int jbase = (t & 3) * 32;
    const float* lg = stud + (size_t)(b * NC + cls) * 16384 + i * 128;

    // seed bitmap for this pass
    // pass 0: fgP = es & (L>0.5)   pass 1: ~fgP   pass 2: et   pass 3: ~et
    unsigned inv = (pass & 1) ? 0xffffffffu : 0u;
    unsigned sv;
    if (pass < 2) {
        unsigned fg = 0, m = ew;
        while (m) {
            int bit = __ffs(m) - 1;
            m &= m - 1;
            if (lg[jbase + bit] > 0.5f) fg |= 1u << bit;
        }
        sv = fg ^ inv;
    } else {
        sv = tw ^ inv;
    }
    Sm[t] = sv;
    // barrier also protects esb/etb reads before gT overwrites sbuf
    int any = __syncthreads_or(sv != 0u);

    // ---- Phase 1: horizontal 1D nearest-seed distance via bit ops ----
    {
        int ri = t & 127;
        int qd = t >> 7;
        unsigned W[4];
#pragma unroll
        for (int w = 0; w < 4; w++) W[w] = Sm[ri * 4 + w];
        unsigned Wq = W[qd];
        int lpos = -100000;
        for (int w = qd - 1; w >= 0; w--)
            if (W[w]) { lpos = 32 * w + (31 - __clz(W[w])); break; }
        int rpos = 100000;
        for (int w = qd + 1; w < 4; w++)
            if (W[w]) { rpos = 32 * w + (__ffs(W[w]) - 1); break; }

        int jb = qd * 32;
#pragma unroll 4
        for (int jj = 0; jj < 32; jj++) {
            int j = jb + jj;
            unsigned mL = Wq & (0xFFFFFFFFu >> (31 - jj));
            unsigned mR = Wq >> jj;
            int dl = mL ? (jj - (31 - __clz(mL))) : (j - lpos);
            int dr = mR ? (__ffs(mR) - 1)         : (rpos - j);
            int d  = min(dl, dr);
            gT[j * GS + ri] = (unsigned short)((d > 127) ? 65025 : d * d);
        }
    }
    __syncthreads();

    // ---- Phase 2: sparse ring search at pixels where diff2 != 0 ----
    float acc = 0.f;
    if (any) {
        unsigned m = ew | tw;
        float fcls = (float)cls;
        while (m) {
            int bit = __ffs(m) - 1;
            m &= m - 1;
            int j = jbase + bit;
            float pred = ((ew >> bit) & 1u) ? lg[j] : 0.f;   // L1-hot
            float targ = ((tw >> bit) & 1u) ? fcls : 0.f;
            float d = pred - targ;
            const unsigned short* g = gT + j * GS;
            int best = g[i];
#pragma unroll 1
            for (int r = 1; r < 128; r++) {
                int r2 = r * r;
                if (r2 >= best) break;
                int lo = (r <= i)      ? (int)g[i - r] : 70000;
                int hi = (i + r < 128) ? (int)g[i + r] : 70000;
                best = min(best, min(lo, hi) + r2);
            }
            float dt2 = (best < 40000) ? (float)best : 0.f;
            acc += d * d * dt2;
        }
    }

    // warp-shuffle reduction
#pragma unroll
    for (int o = 16; o; o >>= 1) acc += __shfl_down_sync(0xffffffffu, acc, o);
    if ((t & 31) == 0) s_warp[t >> 5] = acc;
    __syncthreads();

    if (t == 0) {
        float tot = 0.f;
#pragma unroll
        for (int k = 0; k < 16; k++) tot += s_warp[k];
        g_part[bid] = tot;
        __threadfence();
        if (atomicAdd(&g_counter, 1) == NPAIR * 4 - 1) {
            __threadfence();
            volatile float* vp = g_part;
            float sum = 0.f;
            for (int p = 0; p < NPAIR; p++) {
                float hd = (vp[4 * p + 0] + vp[4 * p + 1] +
                            vp[4 * p + 2] + vp[4 * p + 3]) * (1.f / 16384.f);
                sum += logf(hd + 1.f);
            }
            out[0] = 0.5f * sum;   // (1 - LOSS_WEIGHT) * sum
            g_counter = 0;         // self-reset -> deterministic replays
        }
    }
}

extern "C" void kernel_launch(void* const* d_in, const int* in_sizes, int n_in,
                              void* d_out, int out_size) {
    const float* stud  = (const float*)d_in[0];
    const float* teach = (const float*)d_in[1];
    float* out = (float*)d_out;
    fused_kernel<<<NCTA, NTHR>>>(stud, teach, out);
}

// round 7
// speedup vs baseline: 8.8463x; 1.2448x over previous
#include <cuda_runtime.h>
#include <math.h>

#define NB 2
#define NC 14
#define NCLS 13          // classes 1..13
#define NPAIR (NB*NCLS)  // 26
#define GS 130           // u16 stride for gT (odd u16 count -> conflict-free)
#define NCTA 148
#define NTHR 512
#define NLBL (2*NB*16384)   // 65536 labels (student+teacher)
#define BIGD 70000

// per-pixel argmax labels: [src(0=stud,1=teach)][b][16384 pixels]
__device__ __align__(16) unsigned char g_pred[NLBL];
__device__ float g_part[NPAIR * 4];
__device__ int   g_counter = 0;   // finish counter (self-resetting)
__device__ int   g_cnt     = 0;   // barrier ticket counter (self-resetting)
__device__ int   g_release = 0;   // barrier sense flag (flips each launch)

// pack 4 byte-compare results into a nibble (bit0 = lowest byte)
__device__ __forceinline__ unsigned nib4(unsigned u, unsigned patt) {
    return ((__vcmpeq4(u, patt) & 0x01010101u) * 0x01020408u) >> 24;
}

__global__ void __launch_bounds__(NTHR, 1)
fused_kernel(const float* __restrict__ stud,
             const float* __restrict__ teach,
             float* __restrict__ out) {
    extern __shared__ unsigned char smem[];
    // [0,33280)        gT[col j][row i] u16 squared 1D distances
    // [33280,66048)    list (u16 x 16384); early-aliased: segS/segT/esb/etb
    // [66048,68096)    Sm seed bitmap (512 u32)
    unsigned short* gT   = (unsigned short*)smem;
    unsigned short* list = (unsigned short*)(smem + 33280);
    unsigned*       segS = (unsigned*)(smem + 33280);
    unsigned*       segT = segS + 512;
    unsigned*       esb  = segT + 512;
    unsigned*       etb  = esb + 512;
    unsigned*       Sm   = (unsigned*)(smem + 33280 + 32768);
    __shared__ float s_warp[16];
    __shared__ int   s_wsum[16];

    int t   = threadIdx.x;
    int bid = blockIdx.x;

    // read barrier sense BEFORE any arrival can flip it
    int my_sense = 0;
    if (t == 0) my_sense = *(volatile int*)&g_release;

    // ---- Stage A: per-pixel argmax over C=14 (front-batched loads) ----
    int gid = bid * NTHR + t;
    if (gid < NLBL) {
        int src = gid >> 15;
        int rem = gid & 32767;               // b*16384 + pix
        const float* base = (src ? teach : stud) +
                            (size_t)(rem >> 14) * NC * 16384 + (rem & 16383);
        float v[NC];
#pragma unroll
        for (int c = 0; c < NC; c++) v[c] = base[(size_t)c * 16384];
        float best = v[0];
        int bi = 0;
#pragma unroll
        for (int c = 1; c < NC; c++)
            if (v[c] > best) { best = v[c]; bi = c; }
        g_pred[gid] = (unsigned char)bi;
    }

    // ---- grid-wide sense-reversing barrier (148 co-resident CTAs) ----
    __threadfence();
    __syncthreads();
    if (t == 0) {
        __threadfence();
        int ticket = atomicAdd(&g_cnt, 1);
        if (ticket == NCTA - 1) {
            g_cnt = 0;
            __threadfence();
            atomicExch(&g_release, my_sense ^ 1);
        } else {
            while (*(volatile int*)&g_release == my_sense) __nanosleep(32);
        }
        __threadfence();
    }
    __syncthreads();

    if (bid >= NPAIR * 4) return;            // 44 helper CTAs done

    // ---- Stage B: one CTA per (pair, pass) ----
    int pair = bid >> 2;
    int pass = bid & 3;
    int b    = pair / NCLS;
    int cls  = 1 + (pair % NCLS);

    // build seg bitmaps from labels (threads 0-127, row = t)
    if (t < 128) {
        const uint4* PS = (const uint4*)(g_pred + (size_t)b        * 16384) + t * 8;
        const uint4* PT = (const uint4*)(g_pred + (size_t)(NB + b) * 16384) + t * 8;
        unsigned patt = (unsigned)cls * 0x01010101u;
#pragma unroll
        for (int w = 0; w < 4; w++) {
            uint4 a = PS[w * 2], c4 = PS[w * 2 + 1];
            segS[t * 4 + w] =  nib4(a.x, patt)        | (nib4(a.y, patt) << 4)  |
                              (nib4(a.z, patt) << 8)  | (nib4(a.w, patt) << 12) |
                              (nib4(c4.x, patt) << 16)| (nib4(c4.y, patt) << 20)|
                              (nib4(c4.z, patt) << 24)| (nib4(c4.w, patt) << 28);
            uint4 d4 = PT[w * 2], e4 = PT[w * 2 + 1];
            segT[t * 4 + w] =  nib4(d4.x, patt)        | (nib4(d4.y, patt) << 4)  |
                              (nib4(d4.z, patt) << 8)  | (nib4(d4.w, patt) << 12) |
                              (nib4(e4.x, patt) << 16)| (nib4(e4.y, patt) << 20)|
                              (nib4(e4.z, patt) << 24)| (nib4(e4.w, patt) << 28);
        }
    }
    __syncthreads();

    // edge masks: m & ~erosion(m), cross SE, borders erode
    if (t < 128) {
#pragma unroll
        for (int rep = 0; rep < 2; rep++) {
            const unsigned* seg = rep ? segT : segS;
            unsigned*       eo  = rep ? etb  : esb;
            unsigned cur[4], up[4], dn[4];
#pragma unroll
            for (int w = 0; w < 4; w++) {
                cur[w] = seg[t * 4 + w];
                up[w]  = (t > 0)   ? seg[(t - 1) * 4 + w] : 0u;
                dn[w]  = (t < 127) ? seg[(t + 1) * 4 + w] : 0u;
            }
#pragma unroll
            for (int w = 0; w < 4; w++) {
                unsigned lft = (cur[w] << 1) | (w > 0 ? (cur[w - 1] >> 31) : 0u);
                unsigned rgt = (cur[w] >> 1) | (w < 3 ? (cur[w + 1] << 31) : 0u);
                unsigned er  = cur[w] & up[w] & dn[w] & lft & rgt;
                eo[t * 4 + w] = cur[w] & ~er;
            }
        }
    }
    __syncthreads();

    // word t: row i = t>>2, cols (t&3)*32 .. +31
    unsigned ew = esb[t];
    unsigned tw = etb[t];
    int i_row = t >> 2;
    int jbase = (t & 3) * 32;
    const float* lgb = stud + (size_t)(b * NC + cls) * 16384;

    // seed bitmap for this pass
    // pass 0: fgP = es & (L>0.5)   pass 1: ~fgP   pass 2: et   pass 3: ~et
    unsigned inv = (pass & 1) ? 0xffffffffu : 0u;
    unsigned sv;
    if (pass < 2) {
        unsigned fg = 0, m = ew;
        while (m) {
            int bit = __ffs(m) - 1;
            m &= m - 1;
            if (lgb[i_row * 128 + jbase + bit] > 0.5f) fg |= 1u << bit;
        }
        sv = fg ^ inv;
    } else {
        sv = tw ^ inv;
    }
    Sm[t] = sv;
    // after this barrier seg region is dead -> list may overwrite it
    int any = __syncthreads_or(sv != 0u);

    // ---- Compaction: deterministic list of pixels where diff2 != 0 ----
    int n_tot;
    {
        unsigned m = ew | tw;
        int cnt = __popc(m);
        int lane = t & 31, wid = t >> 5;
        int pre = cnt;
#pragma unroll
        for (int o = 1; o < 32; o <<= 1) {
            int v = __shfl_up_sync(0xffffffffu, pre, o);
            if (lane >= o) pre += v;
        }
        if (lane == 31) s_wsum[wid] = pre;
        __syncthreads();
        int wbase = 0;
        for (int w = 0; w < wid; w++) wbase += s_wsum[w];
        n_tot = 0;
#pragma unroll
        for (int w = 0; w < 16; w++) n_tot += s_wsum[w];
        int ofs = wbase + pre - cnt;
        while (m) {
            int bit = __ffs(m) - 1;
            m &= m - 1;
            int j = jbase + bit;
            list[ofs++] = (unsigned short)(((unsigned)i_row << 9) |
                                           ((unsigned)j << 2)     |
                                           ((ew >> bit) & 1u)     |
                                           (((tw >> bit) & 1u) << 1));
        }
    }

    // ---- Phase 1: horizontal 1D nearest-seed distance via bit ops ----
    {
        int ri = t & 127;
        int qd = t >> 7;
        unsigned W[4];
#pragma unroll
        for (int w = 0; w < 4; w++) W[w] = Sm[ri * 4 + w];
        unsigned Wq = W[qd];
        int lpos = -100000;
        for (int w = qd - 1; w >= 0; w--)
            if (W[w]) { lpos = 32 * w + (31 - __clz(W[w])); break; }
        int rpos = 100000;
        for (int w = qd + 1; w < 4; w++)
            if (W[w]) { rpos = 32 * w + (__ffs(W[w]) - 1); break; }

        int jb = qd * 32;
#pragma unroll 4
        for (int jj = 0; jj < 32; jj++) {
            int j = jb + jj;
            unsigned mL = Wq & (0xFFFFFFFFu >> (31 - jj));
            unsigned mR = Wq >> jj;
            int dl = mL ? (jj - (31 - __clz(mL))) : (j - lpos);
            int dr = mR ? (__ffs(mR) - 1)         : (rpos - j);
            int d  = min(dl, dr);
            gT[j * GS + ri] = (unsigned short)((d > 127) ? 65025 : d * d);
        }
    }
    __syncthreads();   // list + gT complete

    // ---- Phase 2: balanced sparse ring search over the list ----
    float acc = 0.f;
    if (any) {
        float fcls = (float)cls;
        for (int k = t; k < n_tot; k += NTHR) {
            unsigned e = list[k];
            int i = e >> 9;
            int j = (e >> 2) & 127;
            float pred = (e & 1u) ? lgb[i * 128 + j] : 0.f;   // L1/L2-hot
            float targ = (e & 2u) ? fcls : 0.f;
            float d = pred - targ;
            const unsigned short* g = gT + j * GS;
            int best = g[i];
            int lo = (i >= 1)    ? (int)g[i - 1] : BIGD;
            int hi = (i + 1 < 128) ? (int)g[i + 1] : BIGD;
#pragma unroll 1
            for (int r = 1; r * r < best; r++) {
                int cand = min(lo, hi) + r * r;
                lo = (i >= r + 1)      ? (int)g[i - r - 1] : BIGD;  // prefetch r+1
                hi = (i + r + 1 < 128) ? (int)g[i + r + 1] : BIGD;
                best = min(best, cand);
            }
            float dt2 = (best < 40000) ? (float)best : 0.f;
            acc += d * d * dt2;
        }
    }

    // warp-shuffle reduction
#pragma unroll
    for (int o = 16; o; o >>= 1) acc += __shfl_down_sync(0xffffffffu, acc, o);
    if ((t & 31) == 0) s_warp[t >> 5] = acc;
    __syncthreads();

    // ---- finish: last CTA's warp 0 does the parallel log-combine ----
    if (t < 32) {
        if (t == 0) {
            float tot = 0.f;
#pragma unroll
            for (int k = 0; k < 16; k++) tot += s_warp[k];
            g_part[bid] = tot;
            __threadfence();
        }
        int last = 0;
        if (t == 0) last = (atomicAdd(&g_counter, 1) == NPAIR * 4 - 1);
        last = __shfl_sync(0xffffffffu, last, 0);
        if (last) {
            __threadfence();
            float v = 0.f;
            if (t < NPAIR) {
                volatile float* vp = g_part;
                float hd = (vp[4 * t + 0] + vp[4 * t + 1] +
                            vp[4 * t + 2] + vp[4 * t + 3]) * (1.f / 16384.f);
                v = logf(hd + 1.f);
            }
#pragma unroll
            for (int o = 16; o; o >>= 1)
                v += __shfl_down_sync(0xffffffffu, v, o);
            if (t == 0) {
                out[0] = 0.5f * v;   // (1 - LOSS_WEIGHT) * sum
                g_counter = 0;       // self-reset -> deterministic replays
            }
        }
    }
}

extern "C" void kernel_launch(void* const* d_in, const int* in_sizes, int n_in,
                              void* d_out, int out_size) {
    const float* stud  = (const float*)d_in[0];
    const float* teach = (const float*)d_in[1];
    float* out = (float*)d_out;

    const int SMEM = 33280 + 32768 + 2048;   // 68096 B dynamic
    cudaFuncSetAttribute(fused_kernel,
                         cudaFuncAttributeMaxDynamicSharedMemorySize, SMEM);
    fused_kernel<<<NCTA, NTHR, SMEM>>>(stud, teach, out);
}

// round 8
// speedup vs baseline: 10.0691x; 1.1382x over previous
#include <cuda_runtime.h>
#include <math.h>

#define NB 2
#define NC 14
#define NCLS 13          // classes 1..13
#define NPAIR (NB*NCLS)  // 26
#define GS 130           // u16 stride for gT (odd u16 count -> conflict-free)
#define NCTA 148
#define NTHR 512
#define NLBL (2*NB*16384)   // 65536 pixel-slots (student+teacher)
#define BIGD 70000

// per-(src,b,cls) seg bitmaps, 512 words each
__device__ unsigned g_seg[2 * NB * NCLS * 512];
// per-(b,cls) student logit>0.5 bitmaps
__device__ unsigned g_gt05[NB * NCLS * 512];
__device__ float g_part[NPAIR * 4];
__device__ int   g_counter = 0;   // finish counter (self-resetting)
__device__ int   g_cnt     = 0;   // barrier ticket counter (self-resetting)
__device__ int   g_release = 0;   // barrier sense flag (flips each launch)

__global__ void __launch_bounds__(NTHR, 1)
fused_kernel(const float* __restrict__ stud,
             const float* __restrict__ teach,
             float* __restrict__ out) {
    extern __shared__ unsigned char smem[];
    // [0,33280)        gT[col j][row i] u16 squared 1D distances
    // [33280,35328)    Sm seed bitmap (512 u32)
    // [35328,68096)    list (u16 x 16384); early alias: segS/segT/g05 (6 KB)
    unsigned short* gT   = (unsigned short*)smem;
    unsigned*       Sm   = (unsigned*)(smem + 33280);
    unsigned short* list = (unsigned short*)(smem + 35328);
    unsigned*       segS = (unsigned*)(smem + 35328);
    unsigned*       segT = segS + 512;
    unsigned*       g05  = segT + 512;
    __shared__ float s_warp[16];
    __shared__ int   s_wsum[16];

    int t   = threadIdx.x;
    int bid = blockIdx.x;

    // read barrier sense BEFORE any arrival can flip it
    int my_sense = 0;
    if (t == 0) my_sense = *(volatile int*)&g_release;

    // ---- Stage A: argmax + direct bitmap emission via ballots ----
    int gid = bid * NTHR + t;
    if (gid < NLBL) {                        // warp-aligned boundary
        int src = gid >> 15;
        int rem = gid & 32767;               // b*16384 + pix
        int b   = rem >> 14;
        int pix = rem & 16383;
        const float* base = (src ? teach : stud) +
                            (size_t)b * NC * 16384 + pix;
        float v[NC];
#pragma unroll
        for (int c = 0; c < NC; c++) v[c] = base[(size_t)c * 16384];
        float best = v[0];
        int bi = 0;
#pragma unroll
        for (int c = 1; c < NC; c++)
            if (v[c] > best) { best = v[c]; bi = c; }

        int word = pix >> 5;
        int lane0 = ((t & 31) == 0);
        unsigned* segbase = g_seg + (size_t)((src * NB + b) * NCLS) * 512 + word;
#pragma unroll
        for (int c = 1; c < NC; c++) {
            unsigned m = __ballot_sync(0xffffffffu, bi == c);
            if (lane0) segbase[(c - 1) * 512] = m;
        }
        if (src == 0) {                      // student: logit>0.5 bitmaps
            unsigned* gbase = g_gt05 + (size_t)(b * NCLS) * 512 + word;
#pragma unroll
            for (int c = 1; c < NC; c++) {
                unsigned m = __ballot_sync(0xffffffffu, v[c] > 0.5f);
                if (lane0) gbase[(c - 1) * 512] = m;
            }
        }
    }

    // ---- grid-wide sense-reversing barrier (148 co-resident CTAs) ----
    __threadfence();
    __syncthreads();
    if (t == 0) {
        __threadfence();
        int ticket = atomicAdd(&g_cnt, 1);
        if (ticket == NCTA - 1) {
            g_cnt = 0;
            __threadfence();
            atomicExch(&g_release, my_sense ^ 1);
        } else {
            while (*(volatile int*)&g_release == my_sense) __nanosleep(32);
        }
        __threadfence();
    }
    __syncthreads();

    if (bid >= NPAIR * 4) return;            // 44 helper CTAs done

    // ---- Stage B: one CTA per (pair, pass) ----
    int pair = bid >> 2;
    int pass = bid & 3;
    int b    = pair / NCLS;
    int cls  = 1 + (pair % NCLS);

    // load the three bitmaps (1 word per thread)
    segS[t] = g_seg[(size_t)((0 * NB + b) * NCLS + cls - 1) * 512 + t];
    segT[t] = g_seg[(size_t)((1 * NB + b) * NCLS + cls - 1) * 512 + t];
    g05[t]  = g_gt05[(size_t)(b * NCLS + cls - 1) * 512 + t];
    __syncthreads();

    // word-parallel erosion: word t = (row t>>2, quarter t&3)
    int row = t >> 2, w = t & 3;
    unsigned ew, tw;
    {
        unsigned cs = segS[t];
        unsigned up = (row > 0)   ? segS[t - 4] : 0u;
        unsigned dn = (row < 127) ? segS[t + 4] : 0u;
        unsigned lf = (cs << 1) | (w > 0 ? (segS[t - 1] >> 31) : 0u);
        unsigned rg = (cs >> 1) | (w < 3 ? (segS[t + 1] << 31) : 0u);
        ew = cs & ~(cs & up & dn & lf & rg);

        unsigned ct = segT[t];
        unsigned u2 = (row > 0)   ? segT[t - 4] : 0u;
        unsigned d2 = (row < 127) ? segT[t + 4] : 0u;
        unsigned l2 = (ct << 1) | (w > 0 ? (segT[t - 1] >> 31) : 0u);
        unsigned r2 = (ct >> 1) | (w < 3 ? (segT[t + 1] << 31) : 0u);
        tw = ct & ~(ct & u2 & d2 & l2 & r2);
    }

    // seed bitmap for this pass (all-register)
    // pass 0: fgP = es & gt05   pass 1: ~fgP   pass 2: et   pass 3: ~et
    unsigned inv = (pass & 1) ? 0xffffffffu : 0u;
    unsigned sv  = ((pass < 2) ? (ew & g05[t]) : tw) ^ inv;
    Sm[t] = sv;
    // barrier: after this, seg/g05 region is dead -> list may overwrite
    int any = __syncthreads_or(sv != 0u);

    int jbase = w * 32;
    const float* lgb = stud + (size_t)(b * NC + cls) * 16384;

    // ---- Compaction: deterministic list of pixels where diff2 != 0 ----
    int n_tot;
    {
        unsigned m = ew | tw;
        int cnt = __popc(m);
        int lane = t & 31, wid = t >> 5;
        int pre = cnt;
#pragma unroll
        for (int o = 1; o < 32; o <<= 1) {
            int v = __shfl_up_sync(0xffffffffu, pre, o);
            if (lane >= o) pre += v;
        }
        if (lane == 31) s_wsum[wid] = pre;
        __syncthreads();
        int wbase = 0;
        for (int k = 0; k < wid; k++) wbase += s_wsum[k];
        n_tot = 0;
#pragma unroll
        for (int k = 0; k < 16; k++) n_tot += s_wsum[k];
        int ofs = wbase + pre - cnt;
        while (m) {
            int bit = __ffs(m) - 1;
            m &= m - 1;
            int j = jbase + bit;
            list[ofs++] = (unsigned short)(((unsigned)row << 9) |
                                           ((unsigned)j << 2)   |
                                           ((ew >> bit) & 1u)   |
                                           (((tw >> bit) & 1u) << 1));
        }
    }

    // ---- Phase 1: horizontal 1D nearest-seed distance via bit ops ----
    {
        int ri = t & 127;
        int qd = t >> 7;
        unsigned W[4];
#pragma unroll
        for (int k = 0; k < 4; k++) W[k] = Sm[ri * 4 + k];
        unsigned Wq = W[qd];
        int lpos = -100000;
        for (int k = qd - 1; k >= 0; k--)
            if (W[k]) { lpos = 32 * k + (31 - __clz(W[k])); break; }
        int rpos = 100000;
        for (int k = qd + 1; k < 4; k++)
            if (W[k]) { rpos = 32 * k + (__ffs(W[k]) - 1); break; }

        int jb = qd * 32;
#pragma unroll 4
        for (int jj = 0; jj < 32; jj++) {
            int j = jb + jj;
            unsigned mL = Wq & (0xFFFFFFFFu >> (31 - jj));
            unsigned mR = Wq >> jj;
            int dl = mL ? (jj - (31 - __clz(mL))) : (j - lpos);
            int dr = mR ? (__ffs(mR) - 1)         : (rpos - j);
            int d  = min(dl, dr);
            gT[j * GS + ri] = (unsigned short)((d > 127) ? 65025 : d * d);
        }
    }
    __syncthreads();   // list + gT complete

    // ---- Phase 2: balanced sparse ring search over the list ----
    float acc = 0.f;
    if (any) {
        float fcls = (float)cls;
        for (int k = t; k < n_tot; k += NTHR) {
            unsigned e = list[k];
            int i = e >> 9;
            int j = (e >> 2) & 127;
            float pred = (e & 1u) ? lgb[i * 128 + j] : 0.f;   // L2-hot
            float targ = (e & 2u) ? fcls : 0.f;
            float d = pred - targ;
            const unsigned short* g = gT + j * GS;
            int best = g[i];
            int lo = (i >= 1)      ? (int)g[i - 1] : BIGD;
            int hi = (i + 1 < 128) ? (int)g[i + 1] : BIGD;
#pragma unroll 1
            for (int r = 1; r * r < best; r++) {
                int cand = min(lo, hi) + r * r;
                lo = (i >= r + 1)      ? (int)g[i - r - 1] : BIGD;
                hi = (i + r + 1 < 128) ? (int)g[i + r + 1] : BIGD;
                best = min(best, cand);
            }
            float dt2 = (best < 40000) ? (float)best : 0.f;
            acc += d * d * dt2;
        }
    }

    // warp-shuffle reduction
#pragma unroll
    for (int o = 16; o; o >>= 1) acc += __shfl_down_sync(0xffffffffu, acc, o);
    if ((t & 31) == 0) s_warp[t >> 5] = acc;
    __syncthreads();

    // ---- finish: last CTA's warp 0 does the parallel log-combine ----
    if (t < 32) {
        if (t == 0) {
            float tot = 0.f;
#pragma unroll
            for (int k = 0; k < 16; k++) tot += s_warp[k];
            g_part[bid] = tot;
            __threadfence();
        }
        int last = 0;
        if (t == 0) last = (atomicAdd(&g_counter, 1) == NPAIR * 4 - 1);
        last = __shfl_sync(0xffffffffu, last, 0);
        if (last) {
            __threadfence();
            float v = 0.f;
            if (t < NPAIR) {
                volatile float* vp = g_part;
                float hd = (vp[4 * t + 0] + vp[4 * t + 1] +
                            vp[4 * t + 2] + vp[4 * t + 3]) * (1.f / 16384.f);
                v = logf(hd + 1.f);
            }
#pragma unroll
            for (int o = 16; o; o >>= 1)
                v += __shfl_down_sync(0xffffffffu, v, o);
            if (t == 0) {
                out[0] = 0.5f * v;   // (1 - LOSS_WEIGHT) * sum
                g_counter = 0;       // self-reset -> deterministic replays
            }
        }
    }
}

extern "C" void kernel_launch(void* const* d_in, const int* in_sizes, int n_in,
                              void* d_out, int out_size) {
    const float* stud  = (const float*)d_in[0];
    const float* teach = (const float*)d_in[1];
    float* out = (float*)d_out;

    const int SMEM = 33280 + 2048 + 32768;   // 68096 B dynamic
    cudaFuncSetAttribute(fused_kernel,
                         cudaFuncAttributeMaxDynamicSharedMemorySize, SMEM);
    fused_kernel<<<NCTA, NTHR, SMEM>>>(stud, teach, out);
}